// round 10
// baseline (speedup 1.0000x reference)
#include <cuda_runtime.h>
#include <cuda_bf16.h>
#include <math.h>

#define N_NODES 50000
#define N_EDGES 600000
#define DIM 128
#define NUM_CLASSES 10
#define EPSF 1e-15f
#define MAX_NORM (1.0f - 1e-5f)

#define KP 64                      // k-pairs
#define XTP 50048                  // node pitch for pair-packed xT (64*782)
#define FT_PITCH 129
#define MM_TILES ((N_NODES + 63) / 64)   // 782
#define MM_GRID 296
#define MM_SMEM ((KP * DIM + KP * 64) * 8)   // Wsh 64KB + Tsh 32KB = 96KB

#define CSR_BLOCKS 49
#define CSR_THREADS 1024

typedef unsigned long long u64;

// scratch (device globals: no allocation allowed)
__device__ float g_y[N_NODES * DIM];
__device__ float g_agg[N_NODES * DIM];
__device__ u64   g_xTp[KP * XTP];        // (t[2kp][n], t[2kp+1][n])
__device__ u64   g_Wp1[KP * DIM];        // (W[j][2kp], W[j][2kp+1]) at [kp*128+j]
__device__ u64   g_Wp2[KP * DIM];
__device__ int   g_mult;
__device__ int   g_count[N_NODES];
__device__ int   g_cursor[N_NODES];
__device__ int   g_rowstart[N_NODES + 1];
__device__ int   g_bsum[CSR_BLOCKS];
__device__ volatile unsigned g_bar_gen;   // monotonic across graph replays
__device__ unsigned g_bar_cnt;            // self-resets
__device__ int   g_esrc[N_EDGES];

// ---------------------------------------------------------------------------
// packed fp32x2 helpers (Blackwell FFMA2 — PTX-only)
__device__ __forceinline__ u64 fma2(u64 a, u64 b, u64 c) {
    u64 d;
    asm("fma.rn.f32x2 %0, %1, %2, %3;" : "=l"(d) : "l"(a), "l"(b), "l"(c));
    return d;
}
__device__ __forceinline__ u64 pack2(float lo, float hi) {
    u64 r;
    asm("mov.b64 %0, {%1, %2};" : "=l"(r) : "f"(lo), "f"(hi));
    return r;
}
__device__ __forceinline__ void unpack2(u64 v, float& lo, float& hi) {
    asm("mov.b64 {%0, %1}, %2;" : "=f"(lo), "=f"(hi) : "l"(v));
}
__device__ __forceinline__ float sum2(u64 v) {
    float lo, hi;
    unpack2(v, lo, hi);
    return lo + hi;
}

// ---------------------------------------------------------------------------
// software grid barrier (all CSR_BLOCKS resident: 49 << 148 SMs)
__device__ __forceinline__ void grid_barrier() {
    __syncthreads();
    if (threadIdx.x == 0) {
        __threadfence();
        unsigned my = g_bar_gen;
        unsigned a = atomicAdd(&g_bar_cnt, 1);
        if (a == CSR_BLOCKS - 1) {
            g_bar_cnt = 0;
            __threadfence();
            g_bar_gen = my + 1;
        } else {
            while (g_bar_gen == my) __nanosleep(32);
        }
    }
    __syncthreads();
}

// ---------------------------------------------------------------------------
// Fused CSR build (side stream): detect + zero + hist + scan + bucket scatter.
__global__ void __launch_bounds__(CSR_THREADS)
csr_kernel(const int* __restrict__ e32) {
    const int b = blockIdx.x, t = threadIdx.x;
    const int gid = b * CSR_THREADS + t;
    const int nth = CSR_BLOCKS * CSR_THREADS;

    if (b == 0 && t < 32) {
        int v1 = e32[2 * t + 1];
        int bad = __any_sync(0xffffffffu, v1 != 0);
        if (t == 0) g_mult = bad ? 1 : 2;
    }
    if (gid < N_NODES) g_count[gid] = 0;
    grid_barrier();

    const int m = g_mult;
    for (int e = gid; e < N_EDGES; e += nth) {
        int dst = e32[(long long)(N_EDGES + e) * m];
        atomicAdd(&g_count[dst], 1);
    }
    grid_barrier();

    __shared__ int wsum[32];
    __shared__ int part[2];
    const int lane = t & 31, w = t >> 5;
    int v = (gid < N_NODES) ? g_count[gid] : 0;
    int x = v;
#pragma unroll
    for (int d = 1; d < 32; d <<= 1) {
        int y = __shfl_up_sync(0xffffffffu, x, d);
        if (lane >= d) x += y;
    }
    if (lane == 31) wsum[w] = x;
    __syncthreads();
    if (w == 0) {
        int s = wsum[lane];
#pragma unroll
        for (int d = 1; d < 32; d <<= 1) {
            int y = __shfl_up_sync(0xffffffffu, s, d);
            if (lane >= d) s += y;
        }
        wsum[lane] = s;
    }
    __syncthreads();
    int excl = x - v + (w ? wsum[w - 1] : 0);
    if (t == CSR_THREADS - 1) g_bsum[b] = excl + v;
    grid_barrier();

    if (t < 64) {
        int pv = (t < b) ? g_bsum[t] : 0;
#pragma unroll
        for (int d = 16; d > 0; d >>= 1)
            pv += __shfl_xor_sync(0xffffffffu, pv, d);
        if (lane == 0) part[w] = pv;
    }
    __syncthreads();
    const int boff = part[0] + part[1];
    if (gid < N_NODES) {
        int rv = excl + boff;
        g_rowstart[gid] = rv;
        g_cursor[gid] = rv;
    }
    if (gid == 0) g_rowstart[N_NODES] = N_EDGES;
    grid_barrier();

    for (int e = gid; e < N_EDGES; e += nth) {
        int src = e32[(long long)e * m];
        int dst = e32[(long long)(N_EDGES + e) * m];
        int pos = atomicAdd(&g_cursor[dst], 1);
        g_esrc[pos] = src;
    }
}

// ---------------------------------------------------------------------------
// wprep: transpose W1,W2 into k-pair layout Wp[kp*128 + j] = (W[j][2kp], W[j][2kp+1])
__global__ void __launch_bounds__(256)
wprep_kernel(const float* __restrict__ W1, const float* __restrict__ W2,
             u64* __restrict__ Wp1, u64* __restrict__ Wp2) {
    __shared__ float s[32 * FT_PITCH];
    const int mtx = blockIdx.x >> 2;
    const int j0 = (blockIdx.x & 3) * 32;
    const float* W = mtx ? W2 : W1;
    u64* Wp = mtx ? Wp2 : Wp1;
    const int tid = threadIdx.x;

#pragma unroll
    for (int q = 0; q < 4; q++) {
        int idx = q * 256 + tid;          // 0..1023 float4s
        int jj = idx >> 5, k4 = idx & 31;
        float4 v = __ldg((const float4*)&W[(j0 + jj) * DIM + k4 * 4]);
        float* sr = &s[jj * FT_PITCH + k4 * 4];
        sr[0] = v.x; sr[1] = v.y; sr[2] = v.z; sr[3] = v.w;
    }
    __syncthreads();
#pragma unroll
    for (int q = 0; q < 8; q++) {
        int idx = q * 256 + tid;          // 0..2047
        int kp = idx >> 5, jj = idx & 31;
        Wp[kp * DIM + j0 + jj] =
            pack2(s[jj * FT_PITCH + 2 * kp], s[jj * FT_PITCH + 2 * kp + 1]);
    }
}

// ---------------------------------------------------------------------------
// facT: 32-node tile -> (optional logmap0 factor) -> k-pair transposed write.
__global__ void __launch_bounds__(256)
facT_kernel(const float* __restrict__ in, u64* __restrict__ xTp, int do_norm) {
    __shared__ float s[32 * FT_PITCH];
    __shared__ float facs[32];
    const int tid = threadIdx.x, lane = tid & 31, w = tid >> 5;
    const int node0 = blockIdx.x * 32;

#pragma unroll
    for (int q = 0; q < 4; q++) {
        int idx = q * 256 + tid;
        int n = idx >> 5, c4 = idx & 31;
        float4 v = make_float4(0.f, 0.f, 0.f, 0.f);
        if (node0 + n < N_NODES)
            v = __ldg((const float4*)&in[(node0 + n) * DIM + c4 * 4]);
        float* sr = &s[n * FT_PITCH + c4 * 4];
        sr[0] = v.x; sr[1] = v.y; sr[2] = v.z; sr[3] = v.w;
    }
    __syncthreads();

    if (do_norm) {
#pragma unroll
        for (int j = 0; j < 4; j++) {
            int n = w * 4 + j;
            const float* sr = &s[n * FT_PITCH];
            float a0 = sr[lane], a1 = sr[lane + 32];
            float a2 = sr[lane + 64], a3 = sr[lane + 96];
            float ss = a0 * a0 + a1 * a1 + a2 * a2 + a3 * a3;
            ss += __shfl_xor_sync(0xffffffff, ss, 16);
            ss += __shfl_xor_sync(0xffffffff, ss, 8);
            ss += __shfl_xor_sync(0xffffffff, ss, 4);
            ss += __shfl_xor_sync(0xffffffff, ss, 2);
            ss += __shfl_xor_sync(0xffffffff, ss, 1);
            if (lane == 0) {
                float nn = fmaxf(sqrtf(ss), EPSF);
                facs[n] = atanhf(fminf(nn, MAX_NORM)) / nn;
            }
        }
    } else {
        if (tid < 32) facs[tid] = 1.0f;
    }
    __syncthreads();

    const int n = node0 + lane;
    const bool ok = n < N_NODES;
    const float fl = facs[lane];
#pragma unroll
    for (int i = 0; i < 8; i++) {
        int kp = w + 8 * i;
        float vlo = fl * s[lane * FT_PITCH + 2 * kp];
        float vhi = fl * s[lane * FT_PITCH + 2 * kp + 1];
        if (ok) xTp[kp * XTP + n] = pack2(vlo, vhi);
    }
}

// ---------------------------------------------------------------------------
// mm: y = expmap0( t @ W^T + b ). k-pair packed operands; software-pipelined:
// next kp's W/T loads issued before current kp's 32 FFMA2s.
__global__ void __launch_bounds__(256, 2)
mm_kernel(const u64* __restrict__ xTp, const u64* __restrict__ Wp,
          const float* __restrict__ bias, float* __restrict__ y) {
    extern __shared__ u64 sm8[];
    u64* Wsh = sm8;                // [kp][j], 64x128
    u64* Tsh = sm8 + KP * DIM;     // [kp][n], 64x64

    const int tid = threadIdx.x, lane = tid & 31, w = tid >> 5;

    {
        const ulonglong2* wg = (const ulonglong2*)Wp;
        ulonglong2* ws = (ulonglong2*)Wsh;
        for (int i = tid; i < KP * DIM / 2; i += 256) ws[i] = wg[i];
    }
    const float b0 = __ldg(&bias[lane]);
    const float b1 = __ldg(&bias[lane + 32]);
    const float b2 = __ldg(&bias[lane + 64]);
    const float b3 = __ldg(&bias[lane + 96]);
    __syncthreads();

    for (int tile = blockIdx.x; tile < MM_TILES; tile += gridDim.x) {
        const int n0 = tile * 64;

        // stage Tsh (coalesced ulonglong2 copies)
#pragma unroll
        for (int q = 0; q < 8; q++) {
            int idx = q * 256 + tid;            // 0..2047 ulonglong2
            int kp = idx >> 5, c2 = idx & 31;
            *(ulonglong2*)&Tsh[kp * 64 + c2 * 2] =
                *(const ulonglong2*)&xTp[kp * XTP + n0 + c2 * 2];
        }
        __syncthreads();

        u64 acc[4][8];
#pragma unroll
        for (int c = 0; c < 4; c++)
#pragma unroll
            for (int p = 0; p < 8; p++) acc[c][p] = 0ULL;

        // software pipeline: preload kp=0
        const u64* wr0 = &Wsh[lane];
        const ulonglong2* tp0 = (const ulonglong2*)&Tsh[8 * w];
        u64 w0 = wr0[0], w1 = wr0[32], w2 = wr0[64], w3 = wr0[96];
        ulonglong2 t0 = tp0[0], t1 = tp0[1], t2 = tp0[2], t3 = tp0[3];

#pragma unroll 1
        for (int kp = 0; kp < KP; kp++) {
            u64 nw0, nw1, nw2, nw3;
            ulonglong2 nt0, nt1, nt2, nt3;
            if (kp < KP - 1) {
                const u64* wrow = &Wsh[(kp + 1) * DIM + lane];
                nw0 = wrow[0]; nw1 = wrow[32]; nw2 = wrow[64]; nw3 = wrow[96];
                const ulonglong2* tp =
                    (const ulonglong2*)&Tsh[(kp + 1) * 64 + 8 * w];
                nt0 = tp[0]; nt1 = tp[1]; nt2 = tp[2]; nt3 = tp[3];
            }
            acc[0][0] = fma2(w0, t0.x, acc[0][0]);
            acc[1][0] = fma2(w1, t0.x, acc[1][0]);
            acc[2][0] = fma2(w2, t0.x, acc[2][0]);
            acc[3][0] = fma2(w3, t0.x, acc[3][0]);
            acc[0][1] = fma2(w0, t0.y, acc[0][1]);
            acc[1][1] = fma2(w1, t0.y, acc[1][1]);
            acc[2][1] = fma2(w2, t0.y, acc[2][1]);
            acc[3][1] = fma2(w3, t0.y, acc[3][1]);
            acc[0][2] = fma2(w0, t1.x, acc[0][2]);
            acc[1][2] = fma2(w1, t1.x, acc[1][2]);
            acc[2][2] = fma2(w2, t1.x, acc[2][2]);
            acc[3][2] = fma2(w3, t1.x, acc[3][2]);
            acc[0][3] = fma2(w0, t1.y, acc[0][3]);
            acc[1][3] = fma2(w1, t1.y, acc[1][3]);
            acc[2][3] = fma2(w2, t1.y, acc[2][3]);
            acc[3][3] = fma2(w3, t1.y, acc[3][3]);
            acc[0][4] = fma2(w0, t2.x, acc[0][4]);
            acc[1][4] = fma2(w1, t2.x, acc[1][4]);
            acc[2][4] = fma2(w2, t2.x, acc[2][4]);
            acc[3][4] = fma2(w3, t2.x, acc[3][4]);
            acc[0][5] = fma2(w0, t2.y, acc[0][5]);
            acc[1][5] = fma2(w1, t2.y, acc[1][5]);
            acc[2][5] = fma2(w2, t2.y, acc[2][5]);
            acc[3][5] = fma2(w3, t2.y, acc[3][5]);
            acc[0][6] = fma2(w0, t3.x, acc[0][6]);
            acc[1][6] = fma2(w1, t3.x, acc[1][6]);
            acc[2][6] = fma2(w2, t3.x, acc[2][6]);
            acc[3][6] = fma2(w3, t3.x, acc[3][6]);
            acc[0][7] = fma2(w0, t3.y, acc[0][7]);
            acc[1][7] = fma2(w1, t3.y, acc[1][7]);
            acc[2][7] = fma2(w2, t3.y, acc[2][7]);
            acc[3][7] = fma2(w3, t3.y, acc[3][7]);
            w0 = nw0; w1 = nw1; w2 = nw2; w3 = nw3;
            t0 = nt0; t1 = nt1; t2 = nt2; t3 = nt3;
        }

        // epilogue: collapse k-halves, +bias, expmap0, store (4 coalesced STG.32)
#pragma unroll
        for (int p = 0; p < 8; p++) {
            float h0 = sum2(acc[0][p]) + b0;
            float h1 = sum2(acc[1][p]) + b1;
            float h2 = sum2(acc[2][p]) + b2;
            float h3 = sum2(acc[3][p]) + b3;
            float ss = h0 * h0 + h1 * h1 + h2 * h2 + h3 * h3;
            ss += __shfl_xor_sync(0xffffffff, ss, 16);
            ss += __shfl_xor_sync(0xffffffff, ss, 8);
            ss += __shfl_xor_sync(0xffffffff, ss, 4);
            ss += __shfl_xor_sync(0xffffffff, ss, 2);
            ss += __shfl_xor_sync(0xffffffff, ss, 1);
            float nn = fmaxf(sqrtf(ss), EPSF);
            float f = tanhf(nn) / nn;
            int node = n0 + 8 * w + p;
            if (node < N_NODES) {
                float* yr = &y[node * DIM + lane];
                yr[0]  = f * h0;
                yr[32] = f * h1;
                yr[64] = f * h2;
                yr[96] = f * h3;
            }
        }
        __syncthreads();
    }
}

// ---------------------------------------------------------------------------
// Warp-level CSR row gather, 8-deep MLP. Returns per-lane float4 sum.
__device__ __forceinline__ float4 gather_row(const int* __restrict__ esrc,
                                             const float* __restrict__ y,
                                             int s, int e, int lane4) {
    float4 a0 = make_float4(0.f, 0.f, 0.f, 0.f);
    float4 a1 = make_float4(0.f, 0.f, 0.f, 0.f);
    float4 a2 = make_float4(0.f, 0.f, 0.f, 0.f);
    float4 a3 = make_float4(0.f, 0.f, 0.f, 0.f);
    int i = s;
    for (; i + 8 <= e; i += 8) {
        int s0 = __ldg(&esrc[i + 0]);
        int s1 = __ldg(&esrc[i + 1]);
        int s2 = __ldg(&esrc[i + 2]);
        int s3 = __ldg(&esrc[i + 3]);
        int s4 = __ldg(&esrc[i + 4]);
        int s5 = __ldg(&esrc[i + 5]);
        int s6 = __ldg(&esrc[i + 6]);
        int s7 = __ldg(&esrc[i + 7]);
        float4 v0 = __ldg((const float4*)&y[s0 * DIM + lane4]);
        float4 v1 = __ldg((const float4*)&y[s1 * DIM + lane4]);
        float4 v2 = __ldg((const float4*)&y[s2 * DIM + lane4]);
        float4 v3 = __ldg((const float4*)&y[s3 * DIM + lane4]);
        float4 v4 = __ldg((const float4*)&y[s4 * DIM + lane4]);
        float4 v5 = __ldg((const float4*)&y[s5 * DIM + lane4]);
        float4 v6 = __ldg((const float4*)&y[s6 * DIM + lane4]);
        float4 v7 = __ldg((const float4*)&y[s7 * DIM + lane4]);
        a0.x += v0.x; a0.y += v0.y; a0.z += v0.z; a0.w += v0.w;
        a1.x += v1.x; a1.y += v1.y; a1.z += v1.z; a1.w += v1.w;
        a2.x += v2.x; a2.y += v2.y; a2.z += v2.z; a2.w += v2.w;
        a3.x += v3.x; a3.y += v3.y; a3.z += v3.z; a3.w += v3.w;
        a0.x += v4.x; a0.y += v4.y; a0.z += v4.z; a0.w += v4.w;
        a1.x += v5.x; a1.y += v5.y; a1.z += v5.z; a1.w += v5.w;
        a2.x += v6.x; a2.y += v6.y; a2.z += v6.z; a2.w += v6.w;
        a3.x += v7.x; a3.y += v7.y; a3.z += v7.z; a3.w += v7.w;
    }
    for (; i + 2 <= e; i += 2) {
        int s0 = __ldg(&esrc[i + 0]);
        int s1 = __ldg(&esrc[i + 1]);
        float4 v0 = __ldg((const float4*)&y[s0 * DIM + lane4]);
        float4 v1 = __ldg((const float4*)&y[s1 * DIM + lane4]);
        a0.x += v0.x; a0.y += v0.y; a0.z += v0.z; a0.w += v0.w;
        a1.x += v1.x; a1.y += v1.y; a1.z += v1.z; a1.w += v1.w;
    }
    if (i < e) {
        int s0 = __ldg(&esrc[i]);
        float4 v0 = __ldg((const float4*)&y[s0 * DIM + lane4]);
        a2.x += v0.x; a2.y += v0.y; a2.z += v0.z; a2.w += v0.w;
    }
    float4 r;
    r.x = (a0.x + a1.x) + (a2.x + a3.x);
    r.y = (a0.y + a1.y) + (a2.y + a3.y);
    r.z = (a0.z + a1.z) + (a2.z + a3.z);
    r.w = (a0.w + a1.w) + (a2.w + a3.w);
    return r;
}

// Layer-1 aggregation fused with relu + logmap0 scaling.
__global__ void __launch_bounds__(256)
gather_kernel(const int* __restrict__ esrc, const int* __restrict__ rs,
              const float* __restrict__ y, float* __restrict__ agg) {
    const int lane = threadIdx.x & 31;
    const int wid  = threadIdx.x >> 5;
    const int node = blockIdx.x * (blockDim.x >> 5) + wid;
    if (node >= N_NODES) return;
    const int s = rs[node];
    const int e = rs[node + 1];
    float4 r = gather_row(esrc, y, s, e, lane * 4);

    r.x = fmaxf(r.x, 0.f); r.y = fmaxf(r.y, 0.f);
    r.z = fmaxf(r.z, 0.f); r.w = fmaxf(r.w, 0.f);

    float ss = r.x * r.x + r.y * r.y + r.z * r.z + r.w * r.w;
    ss += __shfl_xor_sync(0xffffffff, ss, 16);
    ss += __shfl_xor_sync(0xffffffff, ss, 8);
    ss += __shfl_xor_sync(0xffffffff, ss, 4);
    ss += __shfl_xor_sync(0xffffffff, ss, 2);
    ss += __shfl_xor_sync(0xffffffff, ss, 1);
    float n = fmaxf(sqrtf(ss), EPSF);
    float f = atanhf(fminf(n, MAX_NORM)) / n;

    float4 o = make_float4(f * r.x, f * r.y, f * r.z, f * r.w);
    *(float4*)&agg[node * DIM + lane * 4] = o;
}

// Layer-2 aggregation fused with classifier.
__global__ void __launch_bounds__(256)
gather_cls_kernel(const int* __restrict__ esrc, const int* __restrict__ rs,
                  const float* __restrict__ y, const float* __restrict__ Wc,
                  const float* __restrict__ bc, float* __restrict__ out) {
    __shared__ float Wcs[NUM_CLASSES * DIM];
    __shared__ float bcs[NUM_CLASSES];
    const int tid = threadIdx.x;
    for (int i = tid; i < NUM_CLASSES * DIM; i += blockDim.x) Wcs[i] = Wc[i];
    if (tid < NUM_CLASSES) bcs[tid] = bc[tid];
    __syncthreads();

    const int lane = tid & 31;
    const int wid  = tid >> 5;
    const int node = blockIdx.x * (blockDim.x >> 5) + wid;
    if (node >= N_NODES) return;

    const int s = rs[node];
    const int e = rs[node + 1];
    float4 h = gather_row(esrc, y, s, e, lane * 4);

    h.x = fmaxf(h.x, 0.f); h.y = fmaxf(h.y, 0.f);
    h.z = fmaxf(h.z, 0.f); h.w = fmaxf(h.w, 0.f);

    float sq = h.x * h.x + h.y * h.y + h.z * h.z + h.w * h.w;
    sq += __shfl_xor_sync(0xffffffff, sq, 16);
    sq += __shfl_xor_sync(0xffffffff, sq, 8);
    sq += __shfl_xor_sync(0xffffffff, sq, 4);
    sq += __shfl_xor_sync(0xffffffff, sq, 2);
    sq += __shfl_xor_sync(0xffffffff, sq, 1);
    float n = fmaxf(sqrtf(sq), EPSF);
    float f = atanhf(fminf(n, MAX_NORM)) / n;
    float4 t = make_float4(f * h.x, f * h.y, f * h.z, f * h.w);

#pragma unroll
    for (int c = 0; c < NUM_CLASSES; c++) {
        float4 w = *(const float4*)&Wcs[c * DIM + lane * 4];
        float p = t.x * w.x + t.y * w.y + t.z * w.z + t.w * w.w;
        p += __shfl_xor_sync(0xffffffff, p, 16);
        p += __shfl_xor_sync(0xffffffff, p, 8);
        p += __shfl_xor_sync(0xffffffff, p, 4);
        p += __shfl_xor_sync(0xffffffff, p, 2);
        p += __shfl_xor_sync(0xffffffff, p, 1);
        if (lane == 0) out[node * NUM_CLASSES + c] = p + bcs[c];
    }
}

// ---------------------------------------------------------------------------
extern "C" void kernel_launch(void* const* d_in, const int* in_sizes, int n_in,
                              void* d_out, int out_size) {
    const int*   e32 = (const int*)d_in[0];
    const float* x   = (const float*)d_in[1];
    const float* W1  = (const float*)d_in[2];
    const float* b1  = (const float*)d_in[3];
    const float* W2  = (const float*)d_in[4];
    const float* b2  = (const float*)d_in[5];
    const float* Wc  = (const float*)d_in[6];
    const float* bc  = (const float*)d_in[7];
    float* out = (float*)d_out;

    float *y, *agg;
    u64 *xTp, *Wp1, *Wp2;
    int *rs, *es;
    cudaGetSymbolAddress((void**)&y,   g_y);
    cudaGetSymbolAddress((void**)&agg, g_agg);
    cudaGetSymbolAddress((void**)&xTp, g_xTp);
    cudaGetSymbolAddress((void**)&Wp1, g_Wp1);
    cudaGetSymbolAddress((void**)&Wp2, g_Wp2);
    cudaGetSymbolAddress((void**)&rs,  g_rowstart);
    cudaGetSymbolAddress((void**)&es,  g_esrc);

    // one-time host resources (no device memory involved)
    static cudaStream_t s2 = nullptr;
    static cudaEvent_t evF = nullptr, evW = nullptr, evC = nullptr;
    static bool attr_done = false;
    if (!attr_done) {
        attr_done = true;
        cudaStreamCreateWithFlags(&s2, cudaStreamNonBlocking);
        cudaEventCreateWithFlags(&evF, cudaEventDisableTiming);
        cudaEventCreateWithFlags(&evW, cudaEventDisableTiming);
        cudaEventCreateWithFlags(&evC, cudaEventDisableTiming);
        cudaFuncSetAttribute(mm_kernel,
                             cudaFuncAttributeMaxDynamicSharedMemorySize, MM_SMEM);
    }

    const int ftblocks = (N_NODES + 31) / 32;   // 1563
    const int gblocks  = (N_NODES + 7) / 8;

    // fork side stream: W prep + CSR build overlap layer-1 transform
    cudaEventRecord(evF, 0);
    cudaStreamWaitEvent(s2, evF, 0);
    wprep_kernel<<<8, 256, 0, s2>>>(W1, W2, Wp1, Wp2);
    cudaEventRecord(evW, s2);
    csr_kernel<<<CSR_BLOCKS, CSR_THREADS, 0, s2>>>(e32);
    cudaEventRecord(evC, s2);

    // main stream
    facT_kernel<<<ftblocks, 256>>>(x, xTp, 1);
    cudaStreamWaitEvent(0, evW, 0);                    // mm1 needs Wp1
    mm_kernel<<<MM_GRID, 256, MM_SMEM>>>(xTp, Wp1, b1, y);
    cudaStreamWaitEvent(0, evC, 0);                    // gather needs CSR
    gather_kernel<<<gblocks, 256>>>(es, rs, y, agg);   // + relu + logmap0
    facT_kernel<<<ftblocks, 256>>>(agg, xTp, 0);       // pure transpose
    mm_kernel<<<MM_GRID, 256, MM_SMEM>>>(xTp, Wp2, b2, y);
    gather_cls_kernel<<<gblocks, 256>>>(es, rs, y, Wc, bc, out);
}

// round 11
// speedup vs baseline: 1.2312x; 1.2312x over previous
#include <cuda_runtime.h>
#include <cuda_bf16.h>
#include <math.h>

#define N_NODES 50000
#define N_EDGES 600000
#define DIM 128
#define NUM_CLASSES 10
#define EPSF 1e-15f
#define MAX_NORM (1.0f - 1e-5f)

#define KP 64                      // k-pairs
#define XTP 50048                  // node pitch for pair-packed xT (64*782)
#define FT_PITCH 129
#define MM_TILES ((N_NODES + 63) / 64)   // 782
#define MM_GRID 296
#define MM_SMEM ((KP * DIM + KP * 64) * 8)   // Wsh 64KB + Tsh 32KB = 96KB

#define CSR_BLOCKS 49
#define CSR_THREADS 1024

typedef unsigned long long u64;

// scratch (device globals: no allocation allowed)
__device__ float g_y[N_NODES * DIM];
__device__ float g_agg[N_NODES * DIM];
__device__ u64   g_xTp[KP * XTP];        // (t[2kp][n], t[2kp+1][n])
__device__ u64   g_Wp1[KP * DIM];        // (W[j][2kp], W[j][2kp+1]) at [kp*128+j]
__device__ u64   g_Wp2[KP * DIM];
__device__ int   g_mult;
__device__ int   g_count[N_NODES];
__device__ int   g_cursor[N_NODES];
__device__ int   g_rowstart[N_NODES + 1];
__device__ int   g_bsum[CSR_BLOCKS];
__device__ volatile unsigned g_bar_gen;   // monotonic across graph replays
__device__ unsigned g_bar_cnt;            // self-resets
__device__ int   g_esrc[N_EDGES];

// ---------------------------------------------------------------------------
// packed fp32x2 helpers (Blackwell FFMA2 — PTX-only)
__device__ __forceinline__ u64 fma2(u64 a, u64 b, u64 c) {
    u64 d;
    asm("fma.rn.f32x2 %0, %1, %2, %3;" : "=l"(d) : "l"(a), "l"(b), "l"(c));
    return d;
}
__device__ __forceinline__ u64 pack2(float lo, float hi) {
    u64 r;
    asm("mov.b64 %0, {%1, %2};" : "=l"(r) : "f"(lo), "f"(hi));
    return r;
}
__device__ __forceinline__ void unpack2(u64 v, float& lo, float& hi) {
    asm("mov.b64 {%0, %1}, %2;" : "=f"(lo), "=f"(hi) : "l"(v));
}
__device__ __forceinline__ float sum2(u64 v) {
    float lo, hi;
    unpack2(v, lo, hi);
    return lo + hi;
}

// ---------------------------------------------------------------------------
// software grid barrier (all CSR_BLOCKS resident: 49 << 148 SMs)
__device__ __forceinline__ void grid_barrier() {
    __syncthreads();
    if (threadIdx.x == 0) {
        __threadfence();
        unsigned my = g_bar_gen;
        unsigned a = atomicAdd(&g_bar_cnt, 1);
        if (a == CSR_BLOCKS - 1) {
            g_bar_cnt = 0;
            __threadfence();
            g_bar_gen = my + 1;
        } else {
            while (g_bar_gen == my) __nanosleep(32);
        }
    }
    __syncthreads();
}

// ---------------------------------------------------------------------------
// Fused CSR build (side stream): detect + zero + hist + scan + bucket scatter.
__global__ void __launch_bounds__(CSR_THREADS)
csr_kernel(const int* __restrict__ e32) {
    const int b = blockIdx.x, t = threadIdx.x;
    const int gid = b * CSR_THREADS + t;
    const int nth = CSR_BLOCKS * CSR_THREADS;

    if (b == 0 && t < 32) {
        int v1 = e32[2 * t + 1];
        int bad = __any_sync(0xffffffffu, v1 != 0);
        if (t == 0) g_mult = bad ? 1 : 2;
    }
    if (gid < N_NODES) g_count[gid] = 0;
    grid_barrier();

    const int m = g_mult;
    for (int e = gid; e < N_EDGES; e += nth) {
        int dst = e32[(long long)(N_EDGES + e) * m];
        atomicAdd(&g_count[dst], 1);
    }
    grid_barrier();

    __shared__ int wsum[32];
    __shared__ int part[2];
    const int lane = t & 31, w = t >> 5;
    int v = (gid < N_NODES) ? g_count[gid] : 0;
    int x = v;
#pragma unroll
    for (int d = 1; d < 32; d <<= 1) {
        int y = __shfl_up_sync(0xffffffffu, x, d);
        if (lane >= d) x += y;
    }
    if (lane == 31) wsum[w] = x;
    __syncthreads();
    if (w == 0) {
        int s = wsum[lane];
#pragma unroll
        for (int d = 1; d < 32; d <<= 1) {
            int y = __shfl_up_sync(0xffffffffu, s, d);
            if (lane >= d) s += y;
        }
        wsum[lane] = s;
    }
    __syncthreads();
    int excl = x - v + (w ? wsum[w - 1] : 0);
    if (t == CSR_THREADS - 1) g_bsum[b] = excl + v;
    grid_barrier();

    if (t < 64) {
        int pv = (t < b) ? g_bsum[t] : 0;
#pragma unroll
        for (int d = 16; d > 0; d >>= 1)
            pv += __shfl_xor_sync(0xffffffffu, pv, d);
        if (lane == 0) part[w] = pv;
    }
    __syncthreads();
    const int boff = part[0] + part[1];
    if (gid < N_NODES) {
        int rv = excl + boff;
        g_rowstart[gid] = rv;
        g_cursor[gid] = rv;
    }
    if (gid == 0) g_rowstart[N_NODES] = N_EDGES;
    grid_barrier();

    for (int e = gid; e < N_EDGES; e += nth) {
        int src = e32[(long long)e * m];
        int dst = e32[(long long)(N_EDGES + e) * m];
        int pos = atomicAdd(&g_cursor[dst], 1);
        g_esrc[pos] = src;
    }
}

// ---------------------------------------------------------------------------
// wprep: transpose W1,W2 into k-pair layout Wp[kp*128 + j] = (W[j][2kp], W[j][2kp+1])
__global__ void __launch_bounds__(256)
wprep_kernel(const float* __restrict__ W1, const float* __restrict__ W2,
             u64* __restrict__ Wp1, u64* __restrict__ Wp2) {
    __shared__ float s[32 * FT_PITCH];
    const int mtx = blockIdx.x >> 2;
    const int j0 = (blockIdx.x & 3) * 32;
    const float* W = mtx ? W2 : W1;
    u64* Wp = mtx ? Wp2 : Wp1;
    const int tid = threadIdx.x;

#pragma unroll
    for (int q = 0; q < 4; q++) {
        int idx = q * 256 + tid;          // 0..1023 float4s
        int jj = idx >> 5, k4 = idx & 31;
        float4 v = __ldg((const float4*)&W[(j0 + jj) * DIM + k4 * 4]);
        float* sr = &s[jj * FT_PITCH + k4 * 4];
        sr[0] = v.x; sr[1] = v.y; sr[2] = v.z; sr[3] = v.w;
    }
    __syncthreads();
#pragma unroll
    for (int q = 0; q < 8; q++) {
        int idx = q * 256 + tid;          // 0..2047
        int kp = idx >> 5, jj = idx & 31;
        Wp[kp * DIM + j0 + jj] =
            pack2(s[jj * FT_PITCH + 2 * kp], s[jj * FT_PITCH + 2 * kp + 1]);
    }
}

// ---------------------------------------------------------------------------
// facT: 32-node tile -> (optional logmap0 factor) -> k-pair transposed write.
__global__ void __launch_bounds__(256)
facT_kernel(const float* __restrict__ in, u64* __restrict__ xTp, int do_norm) {
    __shared__ float s[32 * FT_PITCH];
    __shared__ float facs[32];
    const int tid = threadIdx.x, lane = tid & 31, w = tid >> 5;
    const int node0 = blockIdx.x * 32;

#pragma unroll
    for (int q = 0; q < 4; q++) {
        int idx = q * 256 + tid;
        int n = idx >> 5, c4 = idx & 31;
        float4 v = make_float4(0.f, 0.f, 0.f, 0.f);
        if (node0 + n < N_NODES)
            v = __ldg((const float4*)&in[(node0 + n) * DIM + c4 * 4]);
        float* sr = &s[n * FT_PITCH + c4 * 4];
        sr[0] = v.x; sr[1] = v.y; sr[2] = v.z; sr[3] = v.w;
    }
    __syncthreads();

    if (do_norm) {
#pragma unroll
        for (int j = 0; j < 4; j++) {
            int n = w * 4 + j;
            const float* sr = &s[n * FT_PITCH];
            float a0 = sr[lane], a1 = sr[lane + 32];
            float a2 = sr[lane + 64], a3 = sr[lane + 96];
            float ss = a0 * a0 + a1 * a1 + a2 * a2 + a3 * a3;
            ss += __shfl_xor_sync(0xffffffff, ss, 16);
            ss += __shfl_xor_sync(0xffffffff, ss, 8);
            ss += __shfl_xor_sync(0xffffffff, ss, 4);
            ss += __shfl_xor_sync(0xffffffff, ss, 2);
            ss += __shfl_xor_sync(0xffffffff, ss, 1);
            if (lane == 0) {
                float nn = fmaxf(sqrtf(ss), EPSF);
                facs[n] = atanhf(fminf(nn, MAX_NORM)) / nn;
            }
        }
    } else {
        if (tid < 32) facs[tid] = 1.0f;
    }
    __syncthreads();

    const int n = node0 + lane;
    const bool ok = n < N_NODES;
    const float fl = facs[lane];
#pragma unroll
    for (int i = 0; i < 8; i++) {
        int kp = w + 8 * i;
        float vlo = fl * s[lane * FT_PITCH + 2 * kp];
        float vhi = fl * s[lane * FT_PITCH + 2 * kp + 1];
        if (ok) xTp[kp * XTP + n] = pack2(vlo, vhi);
    }
}

// ---------------------------------------------------------------------------
// mm: y = expmap0( t @ W^T + b ). k-pair packed operands.
// Thread owns cols {lane, lane+32, lane+64, lane+96}: W reads are 4 LDS.64s
// with 8B lane stride = 2 wavefronts each (structural minimum, no conflicts).
// (Round-9 proven version: unroll-2, ptxas-scheduled.)
__global__ void __launch_bounds__(256, 2)
mm_kernel(const u64* __restrict__ xTp, const u64* __restrict__ Wp,
          const float* __restrict__ bias, float* __restrict__ y) {
    extern __shared__ u64 sm8[];
    u64* Wsh = sm8;                // [kp][j], 64x128
    u64* Tsh = sm8 + KP * DIM;     // [kp][n], 64x64

    const int tid = threadIdx.x, lane = tid & 31, w = tid >> 5;

    {
        const ulonglong2* wg = (const ulonglong2*)Wp;
        ulonglong2* ws = (ulonglong2*)Wsh;
        for (int i = tid; i < KP * DIM / 2; i += 256) ws[i] = wg[i];
    }
    const float b0 = __ldg(&bias[lane]);
    const float b1 = __ldg(&bias[lane + 32]);
    const float b2 = __ldg(&bias[lane + 64]);
    const float b3 = __ldg(&bias[lane + 96]);
    __syncthreads();

    for (int tile = blockIdx.x; tile < MM_TILES; tile += gridDim.x) {
        const int n0 = tile * 64;

        // stage Tsh (coalesced ulonglong2 copies)
#pragma unroll
        for (int q = 0; q < 8; q++) {
            int idx = q * 256 + tid;            // 0..2047 ulonglong2
            int kp = idx >> 5, c2 = idx & 31;
            *(ulonglong2*)&Tsh[kp * 64 + c2 * 2] =
                *(const ulonglong2*)&xTp[kp * XTP + n0 + c2 * 2];
        }
        __syncthreads();

        u64 acc[4][8];
#pragma unroll
        for (int c = 0; c < 4; c++)
#pragma unroll
            for (int p = 0; p < 8; p++) acc[c][p] = 0ULL;

#pragma unroll 2
        for (int kp = 0; kp < KP; kp++) {
            const u64* wrow = &Wsh[kp * DIM + lane];
            u64 w0 = wrow[0];
            u64 w1 = wrow[32];
            u64 w2 = wrow[64];
            u64 w3 = wrow[96];
            const ulonglong2* tp = (const ulonglong2*)&Tsh[kp * 64 + 8 * w];
            ulonglong2 t0 = tp[0], t1 = tp[1], t2 = tp[2], t3 = tp[3];
            acc[0][0] = fma2(w0, t0.x, acc[0][0]);
            acc[1][0] = fma2(w1, t0.x, acc[1][0]);
            acc[2][0] = fma2(w2, t0.x, acc[2][0]);
            acc[3][0] = fma2(w3, t0.x, acc[3][0]);
            acc[0][1] = fma2(w0, t0.y, acc[0][1]);
            acc[1][1] = fma2(w1, t0.y, acc[1][1]);
            acc[2][1] = fma2(w2, t0.y, acc[2][1]);
            acc[3][1] = fma2(w3, t0.y, acc[3][1]);
            acc[0][2] = fma2(w0, t1.x, acc[0][2]);
            acc[1][2] = fma2(w1, t1.x, acc[1][2]);
            acc[2][2] = fma2(w2, t1.x, acc[2][2]);
            acc[3][2] = fma2(w3, t1.x, acc[3][2]);
            acc[0][3] = fma2(w0, t1.y, acc[0][3]);
            acc[1][3] = fma2(w1, t1.y, acc[1][3]);
            acc[2][3] = fma2(w2, t1.y, acc[2][3]);
            acc[3][3] = fma2(w3, t1.y, acc[3][3]);
            acc[0][4] = fma2(w0, t2.x, acc[0][4]);
            acc[1][4] = fma2(w1, t2.x, acc[1][4]);
            acc[2][4] = fma2(w2, t2.x, acc[2][4]);
            acc[3][4] = fma2(w3, t2.x, acc[3][4]);
            acc[0][5] = fma2(w0, t2.y, acc[0][5]);
            acc[1][5] = fma2(w1, t2.y, acc[1][5]);
            acc[2][5] = fma2(w2, t2.y, acc[2][5]);
            acc[3][5] = fma2(w3, t2.y, acc[3][5]);
            acc[0][6] = fma2(w0, t3.x, acc[0][6]);
            acc[1][6] = fma2(w1, t3.x, acc[1][6]);
            acc[2][6] = fma2(w2, t3.x, acc[2][6]);
            acc[3][6] = fma2(w3, t3.x, acc[3][6]);
            acc[0][7] = fma2(w0, t3.y, acc[0][7]);
            acc[1][7] = fma2(w1, t3.y, acc[1][7]);
            acc[2][7] = fma2(w2, t3.y, acc[2][7]);
            acc[3][7] = fma2(w3, t3.y, acc[3][7]);
        }

        // epilogue: collapse k-halves, +bias, expmap0, store (4 coalesced STG.32)
#pragma unroll
        for (int p = 0; p < 8; p++) {
            float h0 = sum2(acc[0][p]) + b0;
            float h1 = sum2(acc[1][p]) + b1;
            float h2 = sum2(acc[2][p]) + b2;
            float h3 = sum2(acc[3][p]) + b3;
            float ss = h0 * h0 + h1 * h1 + h2 * h2 + h3 * h3;
            ss += __shfl_xor_sync(0xffffffff, ss, 16);
            ss += __shfl_xor_sync(0xffffffff, ss, 8);
            ss += __shfl_xor_sync(0xffffffff, ss, 4);
            ss += __shfl_xor_sync(0xffffffff, ss, 2);
            ss += __shfl_xor_sync(0xffffffff, ss, 1);
            float nn = fmaxf(sqrtf(ss), EPSF);
            float f = tanhf(nn) / nn;
            int node = n0 + 8 * w + p;
            if (node < N_NODES) {
                float* yr = &y[node * DIM + lane];
                yr[0]  = f * h0;
                yr[32] = f * h1;
                yr[64] = f * h2;
                yr[96] = f * h3;
            }
        }
        __syncthreads();
    }
}

// ---------------------------------------------------------------------------
// Warp-level CSR row gather, 8-deep MLP. Returns per-lane float4 sum.
__device__ __forceinline__ float4 gather_row(const int* __restrict__ esrc,
                                             const float* __restrict__ y,
                                             int s, int e, int lane4) {
    float4 a0 = make_float4(0.f, 0.f, 0.f, 0.f);
    float4 a1 = make_float4(0.f, 0.f, 0.f, 0.f);
    float4 a2 = make_float4(0.f, 0.f, 0.f, 0.f);
    float4 a3 = make_float4(0.f, 0.f, 0.f, 0.f);
    int i = s;
    for (; i + 8 <= e; i += 8) {
        int s0 = __ldg(&esrc[i + 0]);
        int s1 = __ldg(&esrc[i + 1]);
        int s2 = __ldg(&esrc[i + 2]);
        int s3 = __ldg(&esrc[i + 3]);
        int s4 = __ldg(&esrc[i + 4]);
        int s5 = __ldg(&esrc[i + 5]);
        int s6 = __ldg(&esrc[i + 6]);
        int s7 = __ldg(&esrc[i + 7]);
        float4 v0 = __ldg((const float4*)&y[s0 * DIM + lane4]);
        float4 v1 = __ldg((const float4*)&y[s1 * DIM + lane4]);
        float4 v2 = __ldg((const float4*)&y[s2 * DIM + lane4]);
        float4 v3 = __ldg((const float4*)&y[s3 * DIM + lane4]);
        float4 v4 = __ldg((const float4*)&y[s4 * DIM + lane4]);
        float4 v5 = __ldg((const float4*)&y[s5 * DIM + lane4]);
        float4 v6 = __ldg((const float4*)&y[s6 * DIM + lane4]);
        float4 v7 = __ldg((const float4*)&y[s7 * DIM + lane4]);
        a0.x += v0.x; a0.y += v0.y; a0.z += v0.z; a0.w += v0.w;
        a1.x += v1.x; a1.y += v1.y; a1.z += v1.z; a1.w += v1.w;
        a2.x += v2.x; a2.y += v2.y; a2.z += v2.z; a2.w += v2.w;
        a3.x += v3.x; a3.y += v3.y; a3.z += v3.z; a3.w += v3.w;
        a0.x += v4.x; a0.y += v4.y; a0.z += v4.z; a0.w += v4.w;
        a1.x += v5.x; a1.y += v5.y; a1.z += v5.z; a1.w += v5.w;
        a2.x += v6.x; a2.y += v6.y; a2.z += v6.z; a2.w += v6.w;
        a3.x += v7.x; a3.y += v7.y; a3.z += v7.z; a3.w += v7.w;
    }
    for (; i + 2 <= e; i += 2) {
        int s0 = __ldg(&esrc[i + 0]);
        int s1 = __ldg(&esrc[i + 1]);
        float4 v0 = __ldg((const float4*)&y[s0 * DIM + lane4]);
        float4 v1 = __ldg((const float4*)&y[s1 * DIM + lane4]);
        a0.x += v0.x; a0.y += v0.y; a0.z += v0.z; a0.w += v0.w;
        a1.x += v1.x; a1.y += v1.y; a1.z += v1.z; a1.w += v1.w;
    }
    if (i < e) {
        int s0 = __ldg(&esrc[i]);
        float4 v0 = __ldg((const float4*)&y[s0 * DIM + lane4]);
        a2.x += v0.x; a2.y += v0.y; a2.z += v0.z; a2.w += v0.w;
    }
    float4 r;
    r.x = (a0.x + a1.x) + (a2.x + a3.x);
    r.y = (a0.y + a1.y) + (a2.y + a3.y);
    r.z = (a0.z + a1.z) + (a2.z + a3.z);
    r.w = (a0.w + a1.w) + (a2.w + a3.w);
    return r;
}

// Layer-1 aggregation fused with relu + logmap0 scaling.
__global__ void __launch_bounds__(256)
gather_kernel(const int* __restrict__ esrc, const int* __restrict__ rs,
              const float* __restrict__ y, float* __restrict__ agg) {
    const int lane = threadIdx.x & 31;
    const int wid  = threadIdx.x >> 5;
    const int node = blockIdx.x * (blockDim.x >> 5) + wid;
    if (node >= N_NODES) return;
    const int s = rs[node];
    const int e = rs[node + 1];
    float4 r = gather_row(esrc, y, s, e, lane * 4);

    r.x = fmaxf(r.x, 0.f); r.y = fmaxf(r.y, 0.f);
    r.z = fmaxf(r.z, 0.f); r.w = fmaxf(r.w, 0.f);

    float ss = r.x * r.x + r.y * r.y + r.z * r.z + r.w * r.w;
    ss += __shfl_xor_sync(0xffffffff, ss, 16);
    ss += __shfl_xor_sync(0xffffffff, ss, 8);
    ss += __shfl_xor_sync(0xffffffff, ss, 4);
    ss += __shfl_xor_sync(0xffffffff, ss, 2);
    ss += __shfl_xor_sync(0xffffffff, ss, 1);
    float n = fmaxf(sqrtf(ss), EPSF);
    float f = atanhf(fminf(n, MAX_NORM)) / n;

    float4 o = make_float4(f * r.x, f * r.y, f * r.z, f * r.w);
    *(float4*)&agg[node * DIM + lane * 4] = o;
}

// Layer-2 aggregation fused with classifier.
__global__ void __launch_bounds__(256)
gather_cls_kernel(const int* __restrict__ esrc, const int* __restrict__ rs,
                  const float* __restrict__ y, const float* __restrict__ Wc,
                  const float* __restrict__ bc, float* __restrict__ out) {
    __shared__ float Wcs[NUM_CLASSES * DIM];
    __shared__ float bcs[NUM_CLASSES];
    const int tid = threadIdx.x;
    for (int i = tid; i < NUM_CLASSES * DIM; i += blockDim.x) Wcs[i] = Wc[i];
    if (tid < NUM_CLASSES) bcs[tid] = bc[tid];
    __syncthreads();

    const int lane = tid & 31;
    const int wid  = tid >> 5;
    const int node = blockIdx.x * (blockDim.x >> 5) + wid;
    if (node >= N_NODES) return;

    const int s = rs[node];
    const int e = rs[node + 1];
    float4 h = gather_row(esrc, y, s, e, lane * 4);

    h.x = fmaxf(h.x, 0.f); h.y = fmaxf(h.y, 0.f);
    h.z = fmaxf(h.z, 0.f); h.w = fmaxf(h.w, 0.f);

    float sq = h.x * h.x + h.y * h.y + h.z * h.z + h.w * h.w;
    sq += __shfl_xor_sync(0xffffffff, sq, 16);
    sq += __shfl_xor_sync(0xffffffff, sq, 8);
    sq += __shfl_xor_sync(0xffffffff, sq, 4);
    sq += __shfl_xor_sync(0xffffffff, sq, 2);
    sq += __shfl_xor_sync(0xffffffff, sq, 1);
    float n = fmaxf(sqrtf(sq), EPSF);
    float f = atanhf(fminf(n, MAX_NORM)) / n;
    float4 t = make_float4(f * h.x, f * h.y, f * h.z, f * h.w);

#pragma unroll
    for (int c = 0; c < NUM_CLASSES; c++) {
        float4 w = *(const float4*)&Wcs[c * DIM + lane * 4];
        float p = t.x * w.x + t.y * w.y + t.z * w.z + t.w * w.w;
        p += __shfl_xor_sync(0xffffffff, p, 16);
        p += __shfl_xor_sync(0xffffffff, p, 8);
        p += __shfl_xor_sync(0xffffffff, p, 4);
        p += __shfl_xor_sync(0xffffffff, p, 2);
        p += __shfl_xor_sync(0xffffffff, p, 1);
        if (lane == 0) out[node * NUM_CLASSES + c] = p + bcs[c];
    }
}

// ---------------------------------------------------------------------------
extern "C" void kernel_launch(void* const* d_in, const int* in_sizes, int n_in,
                              void* d_out, int out_size) {
    const int*   e32 = (const int*)d_in[0];
    const float* x   = (const float*)d_in[1];
    const float* W1  = (const float*)d_in[2];
    const float* b1  = (const float*)d_in[3];
    const float* W2  = (const float*)d_in[4];
    const float* b2  = (const float*)d_in[5];
    const float* Wc  = (const float*)d_in[6];
    const float* bc  = (const float*)d_in[7];
    float* out = (float*)d_out;

    float *y, *agg;
    u64 *xTp, *Wp1, *Wp2;
    int *rs, *es;
    cudaGetSymbolAddress((void**)&y,   g_y);
    cudaGetSymbolAddress((void**)&agg, g_agg);
    cudaGetSymbolAddress((void**)&xTp, g_xTp);
    cudaGetSymbolAddress((void**)&Wp1, g_Wp1);
    cudaGetSymbolAddress((void**)&Wp2, g_Wp2);
    cudaGetSymbolAddress((void**)&rs,  g_rowstart);
    cudaGetSymbolAddress((void**)&es,  g_esrc);

    // one-time host resources (no device memory involved)
    static cudaStream_t s2 = nullptr;
    static cudaEvent_t evF = nullptr, evW = nullptr, evC = nullptr;
    static bool attr_done = false;
    if (!attr_done) {
        attr_done = true;
        cudaStreamCreateWithFlags(&s2, cudaStreamNonBlocking);
        cudaEventCreateWithFlags(&evF, cudaEventDisableTiming);
        cudaEventCreateWithFlags(&evW, cudaEventDisableTiming);
        cudaEventCreateWithFlags(&evC, cudaEventDisableTiming);
        cudaFuncSetAttribute(mm_kernel,
                             cudaFuncAttributeMaxDynamicSharedMemorySize, MM_SMEM);
    }

    const int ftblocks = (N_NODES + 31) / 32;   // 1563
    const int gblocks  = (N_NODES + 7) / 8;

    // fork side stream: W prep + CSR build overlap layer-1 transform
    cudaEventRecord(evF, 0);
    cudaStreamWaitEvent(s2, evF, 0);
    wprep_kernel<<<8, 256, 0, s2>>>(W1, W2, Wp1, Wp2);
    cudaEventRecord(evW, s2);
    csr_kernel<<<CSR_BLOCKS, CSR_THREADS, 0, s2>>>(e32);
    cudaEventRecord(evC, s2);

    // main stream
    facT_kernel<<<ftblocks, 256>>>(x, xTp, 1);
    cudaStreamWaitEvent(0, evW, 0);                    // mm1 needs Wp1
    mm_kernel<<<MM_GRID, 256, MM_SMEM>>>(xTp, Wp1, b1, y);
    cudaStreamWaitEvent(0, evC, 0);                    // gather needs CSR
    gather_kernel<<<gblocks, 256>>>(es, rs, y, agg);   // + relu + logmap0
    facT_kernel<<<ftblocks, 256>>>(agg, xTp, 0);       // pure transpose
    mm_kernel<<<MM_GRID, 256, MM_SMEM>>>(xTp, Wp2, b2, y);
    gather_cls_kernel<<<gblocks, 256>>>(es, rs, y, Wc, bc, out);
}